// round 16
// baseline (speedup 1.0000x reference)
#include <cuda_runtime.h>
#include <cuda_bf16.h>

// N=1, C=2, H=64, W=64, D=32, radius=(3,3,1), SIGMA_XY=5, SIGMA_IMG=0.1, WEIGHT=1
#define NH 64
#define NW 64
#define ND 32
#define NL (NH * NW * ND)      // 131072

#define TPB  128
#define NBLK 512               // block = (h=2, w=4, d=32) slab = 256 voxels, 2 voxels/thread

// smem tile: tw-major (10, 8, 32) float2 (v, y0): offset = tw*256 + th*32 + td.
// All strides pow2; tap offset = dw*256 + dh*32 + dz (compile-time immediates).
#define SW 256
#define SH 32
#define TSIZE 2560             // 10*8*32; tile[2560] = corner pad (max reachable index)
#define NQUAD (TSIZE / 4)      // 640 quads = exactly 5 passes of 128 threads

#define SENTINEL 1e19f
#define LOG2E 1.4426950408889634f
// v = s * K1, K1 = sqrt(50 * log2(e));  exp2 image exponent = -(vp-vq)^2
#define K1 8.49321805761796f

__device__ float    g_part[NBLK];
__device__ unsigned g_cnt = 0;   // last block resets to 0 (graph-replay safe)

__device__ __forceinline__ float ex2(float x) {   // guaranteed MUFU EX2
    float r;
    asm("ex2.approx.f32 %0, %1;" : "=f"(r) : "f"(x));
    return r;
}

__global__ __launch_bounds__(TPB, 4) void k_all(const float* __restrict__ y,
                                                const float* __restrict__ s,
                                                const float* __restrict__ spacing,
                                                float* __restrict__ out) {
    __shared__ float2 tile[TSIZE + 2];
    __shared__ float  warp_s[4];

    // block -> slab origin (32 h-slabs x 16 w-slabs)
    const int hbase = (blockIdx.x >> 4) << 1;   // 0,2,...,62
    const int wbase = (blockIdx.x & 15) << 2;   // 0,4,...,60

    // ---- vectorized tile loader: 640 quads = 5 full passes, pow2 index math ----
    // Quad q -> (tw, th, td4); stores (v, y) with v = s*K1.
    #pragma unroll
    for (int j = 0; j < 5; ++j) {
        const int q   = threadIdx.x + j * TPB;  // 0..639, exact
        const int tw  = q >> 6;                 // 0..9
        const int th  = (q >> 3) & 7;           // 0..7
        const int td4 = (q & 7) << 2;           // 0,4,...,28
        const int gh  = hbase + th - 3;
        const int gw  = wbase + tw - 3;
        float4 q0 = make_float4(SENTINEL, 0.0f, SENTINEL, 0.0f);
        float4 q1 = q0;
        if (((unsigned)gh < NH) & ((unsigned)gw < NW)) {
            const int gidx = (gh * NW + gw) * ND + td4;    // 16B-aligned
            const float4 a = __ldg((const float4*)(s + gidx));
            const float4 b = __ldg((const float4*)(y + gidx));
            q0 = make_float4(a.x * K1, b.x, a.y * K1, b.y);
            q1 = make_float4(a.z * K1, b.z, a.w * K1, b.w);
        }
        float4* tp = (float4*)&tile[tw * SW + th * SH + td4];
        tp[0] = q0;
        tp[1] = q1;
    }
    if (threadIdx.x == 0) tile[TSIZE] = make_float2(SENTINEL, 0.0f);  // corner pad
    __syncthreads();

    // thread -> 2 voxels: (hl, wl, d) and (hl, wl+2, d); pair offset +2*SW = +512
    const int d  = threadIdx.x & 31;
    const int hl = (threadIdx.x >> 5) & 1;      // 0..1
    const int wl = threadIdx.x >> 6;            // 0..1
    const int h  = hbase + hl;
    const int w0 = wbase + wl;
    const int w1 = w0 + 2;
    const int tb0 = (wl + 3) * SW + (hl + 3) * SH + d;
    const int tb1 = tb0 + 2 * SW;

    const float2 c0a = tile[tb0];
    const float2 c0b = tile[tb1];
    const float vp0 = c0a.x, y0p0 = c0a.y;
    const float vp1 = c0b.x, y0p1 = c0b.y;
    const float m0  = 1.0f - 2.0f * y0p0;       // 1 - dot = y0p + m*y0q  (C=2 softmax)
    const float m1  = 1.0f - 2.0f * y0p1;

    const float sH = __ldg(spacing + 0);
    const float sW = __ldg(spacing + 1);
    const float sD = __ldg(spacing + 2);
    const float aH = sH * sH * (LOG2E / 50.0f);
    const float aW = sW * sW * (LOG2E / 50.0f);
    const float aD = sD * sD * (LOG2E / 50.0f);

    // Register-resident spatial constants: 16 distinct (|dh|,|dw|) combos;
    // the dz=1 factor 2^(-aD) is hoisted out of the loop (scaleZ below).
    float coffs[16];
    #pragma unroll
    for (int ih = 0; ih < 4; ++ih) {
        const float vH = -aH * (float)(ih * ih);
        #pragma unroll
        for (int iw = 0; iw < 4; ++iw)
            coffs[ih * 4 + iw] = fmaf(-aW, (float)(iw * iw), vH);
    }

    // dz=0 -> Ka*/KYa* (always valid); dz=1 -> Kb*/KYb* (valid iff d<31; d=31's
    // dz=1 reads are the analytic-OOB set, masked exactly below).
    float Ka0 = 0.0f, KYa0 = 0.0f, Kb0 = 0.0f, KYb0 = 0.0f;
    float Ka1 = 0.0f, KYa1 = 0.0f, Kb1 = 0.0f, KYb1 = 0.0f;

    // Half-space offsets (73 of 146 non-center taps); each in-bounds pair
    // counted once, doubled below (k and (1-dot) are p<->q symmetric).
    // Sentinel halo (h/w OOB rows) drives ex2 -> exactly 0: branch-free LDS.
    // Two voxels per tap: shared coff, fully independent chains (ILP x2).
    #pragma unroll
    for (int dz = 0; dz <= 1; ++dz) {
        #pragma unroll
        for (int dw = -3; dw <= 3; ++dw) {
            #pragma unroll
            for (int dh = -3; dh <= 3; ++dh) {
                if (dz == 0 && (dw < 0 || (dw == 0 && dh <= 0))) continue;
                const int ih = dh < 0 ? -dh : dh;           // compile-time
                const int iw = dw < 0 ? -dw : dw;           // compile-time
                const int off = dw * SW + dh * SH + dz;     // compile-time
                const float cf = coffs[ih * 4 + iw];
                const float2 cq0 = tile[tb0 + off];
                const float2 cq1 = tile[tb1 + off];
                const float dv0 = vp0 - cq0.x;
                const float dv1 = vp1 - cq1.x;
                const float e0  = fmaf(-dv0, dv0, cf);
                const float e1  = fmaf(-dv1, dv1, cf);
                const float k0  = ex2(e0);
                const float k1  = ex2(e1);
                if (dz == 0) {
                    Ka0 += k0; KYa0 = fmaf(k0, cq0.y, KYa0);
                    Ka1 += k1; KYa1 = fmaf(k1, cq1.y, KYa1);
                } else {
                    Kb0 += k0; KYb0 = fmaf(k0, cq0.y, KYb0);
                    Kb1 += k1; KYb1 = fmaf(k1, cq1.y, KYb1);
                }
            }
        }
    }
    const float maskD = (d < ND - 1) ? 1.0f : 0.0f;
    const float scaleZ = maskD * ex2(-aD);      // dz=1 spatial factor, hoisted
    const float K0  = fmaf(scaleZ, Kb0,  Ka0);
    const float KY0 = fmaf(scaleZ, KYb0, KYa0);
    const float K1v = fmaf(scaleZ, Kb1,  Ka1);
    const float KY1 = fmaf(scaleZ, KYb1, KYa1);
    float acc = 2.0f * ((y0p0 * K0 + m0 * KY0) + (y0p1 * K1v + m1 * KY1));

    // OOB taps (zero-padded unfold): y-term 0; kernel value identical per
    // OOB offset: exp(-0.5*||f(p)||^2). Count analytically, per voxel.
    const int cntH = min(h, 3) + min(NH - 1 - h, 3) + 1;
    const int cntD = min(d, 1) + min(ND - 1 - d, 1) + 1;
    const float sphc = -(aH * (float)(h * h) + aD * (float)(d * d));
    {
        const int cntW0 = min(w0, 3) + min(NW - 1 - w0, 3) + 1;
        const int noob0 = 147 - cntH * cntW0 * cntD;
        if (noob0) {
            const float e = fmaf(-vp0, vp0, fmaf(-aW, (float)(w0 * w0), sphc));
            acc = fmaf((float)noob0, ex2(e), acc);
        }
        const int cntW1 = min(w1, 3) + min(NW - 1 - w1, 3) + 1;
        const int noob1 = 147 - cntH * cntW1 * cntD;
        if (noob1) {
            const float e = fmaf(-vp1, vp1, fmaf(-aW, (float)(w1 * w1), sphc));
            acc = fmaf((float)noob1, ex2(e), acc);
        }
    }

    // ---- block reduction ----
    #pragma unroll
    for (int o = 16; o; o >>= 1) acc += __shfl_down_sync(0xffffffffu, acc, o);
    const int lane = threadIdx.x & 31;
    const int wrp  = threadIdx.x >> 5;
    if (lane == 0) warp_s[wrp] = acc;
    __syncthreads();
    if (threadIdx.x == 0)
        g_part[blockIdx.x] = (warp_s[0] + warp_s[1]) + (warp_s[2] + warp_s[3]);

    // ---- last-block final reduction ----
    __threadfence();
    __shared__ bool is_last;
    if (threadIdx.x == 0)
        is_last = (atomicAdd(&g_cnt, 1u) == NBLK - 1);
    __syncthreads();

    if (is_last) {
        float v = 0.0f;
        #pragma unroll
        for (int j = 0; j < NBLK / TPB; ++j)
            v += g_part[threadIdx.x + j * TPB];
        #pragma unroll
        for (int o = 16; o; o >>= 1) v += __shfl_down_sync(0xffffffffu, v, o);
        if (lane == 0) warp_s[wrp] = v;
        __syncthreads();
        if (threadIdx.x == 0) {
            out[0] = ((warp_s[0] + warp_s[1]) + (warp_s[2] + warp_s[3])) * (1.0f / (float)NL);
            g_cnt = 0;                 // restore for next graph replay
        }
    }
}

extern "C" void kernel_launch(void* const* d_in, const int* in_sizes, int n_in,
                              void* d_out, int out_size) {
    const float* y       = (const float*)d_in[0];  // (1,2,64,64,32) softmax; ch 0 used
    const float* sample  = (const float*)d_in[1];  // (1,1,64,64,32)
    const float* spacing = (const float*)d_in[2];  // (3,1)
    k_all<<<NBLK, TPB>>>(y, sample, spacing, (float*)d_out);
}